// round 16
// baseline (speedup 1.0000x reference)
#include <cuda_runtime.h>
#include <math.h>
#include <stdint.h>

#define Bsz 512
#define Nn  256
#define Hh  128
#define Gg  384   // 3*H

// ---------------- device scratch (no runtime allocs allowed) ----------------
__device__ float g_GI[(size_t)Bsz*Nn*Gg];    // encoder input gates (x@wih+bih)
__device__ float g_enc[(size_t)Bsz*Nn*Hh];   // encoder outputs
__device__ float g_w1e[(size_t)Bsz*Nn*Hh];   // enc_outs @ w1
__device__ float g_h[Bsz*Hh];                // GRU hidden (enc then dec)
__device__ float g_decin[Bsz*Hh];            // decoder input vector
__device__ float g_q[Bsz*Hh];                // hn @ w2
__device__ float g_logp[Bsz];
__device__ unsigned char g_mask[Bsz*Nn];

// ---------------- math helpers (robust to fast-math) ----------------
__device__ __forceinline__ float fsig(float x){
    return 1.0f/(1.0f + exp2f(-1.4426950408889634f*x));
}
__device__ __forceinline__ float ftanh(float x){
    float e = exp2f(2.8853900817779268f*x);     // e^(2x)
    return 1.0f - 2.0f/(e + 1.0f);
}

// ---------------- JAX threefry2x32 (exact, 20 rounds) ----------------
__device__ __forceinline__ unsigned rotl(unsigned v, int s){ return (v<<s)|(v>>(32-s)); }
__device__ __forceinline__ void tfry(unsigned k0, unsigned k1,
                                     unsigned x0, unsigned x1,
                                     unsigned &o0, unsigned &o1){
    unsigned k2 = k0 ^ k1 ^ 0x1BD11BDAu;
    x0 += k0; x1 += k1;
    x0+=x1; x1=rotl(x1,13); x1^=x0;  x0+=x1; x1=rotl(x1,15); x1^=x0;
    x0+=x1; x1=rotl(x1,26); x1^=x0;  x0+=x1; x1=rotl(x1, 6); x1^=x0;
    x0 += k1; x1 += k2 + 1u;
    x0+=x1; x1=rotl(x1,17); x1^=x0;  x0+=x1; x1=rotl(x1,29); x1^=x0;
    x0+=x1; x1=rotl(x1,16); x1^=x0;  x0+=x1; x1=rotl(x1,24); x1^=x0;
    x0 += k2; x1 += k0 + 2u;
    x0+=x1; x1=rotl(x1,13); x1^=x0;  x0+=x1; x1=rotl(x1,15); x1^=x0;
    x0+=x1; x1=rotl(x1,26); x1^=x0;  x0+=x1; x1=rotl(x1, 6); x1^=x0;
    x0 += k0; x1 += k1 + 3u;
    x0+=x1; x1=rotl(x1,17); x1^=x0;  x0+=x1; x1=rotl(x1,29); x1^=x0;
    x0+=x1; x1=rotl(x1,16); x1^=x0;  x0+=x1; x1=rotl(x1,24); x1^=x0;
    x0 += k1; x1 += k2 + 4u;
    x0+=x1; x1=rotl(x1,13); x1^=x0;  x0+=x1; x1=rotl(x1,15); x1^=x0;
    x0+=x1; x1=rotl(x1,26); x1^=x0;  x0+=x1; x1=rotl(x1, 6); x1^=x0;
    x0 += k2; x1 += k0 + 5u;
    o0 = x0; o1 = x1;
}

// ---------------- init: mask=0, h=0, logp=0, dec_input0 ----------------
__global__ __launch_bounds__(256) void init_k(const float* __restrict__ pts,
                                              const float* __restrict__ spw,
                                              const float* __restrict__ spb){
    int b = blockIdx.x, tid = threadIdx.x;
    __shared__ float s0[256], s1[256];
    float2 p = ((const float2*)pts)[b*Nn + tid];
    s0[tid] = p.x; s1[tid] = p.y;
    __syncthreads();
    for (int s = 128; s; s >>= 1){
        if (tid < s){ s0[tid] += s0[tid+s]; s1[tid] += s1[tid+s]; }
        __syncthreads();
    }
    float m0 = s0[0] * (1.0f/256.0f);
    float m1 = s1[0] * (1.0f/256.0f);
    g_mask[b*Nn + tid] = 0;
    if (tid < Hh){
        g_h[b*Hh + tid] = 0.0f;
        g_decin[b*Hh + tid] = m0*spw[tid] + m1*spw[Hh + tid] + spb[tid];
    }
    if (tid == 0) g_logp[b] = 0.0f;
}

// -------- GI = relu(points@fc_w+fc_b) @ enc_wih + enc_bih (fused A) --------
__global__ __launch_bounds__(256) void gemm_gi(const float* __restrict__ pts,
                                               const float* __restrict__ fcw,
                                               const float* __restrict__ fcb,
                                               const float* __restrict__ W,
                                               const float* __restrict__ bias){
    __shared__ __align__(16) float As[16][68];
    __shared__ __align__(16) float Ws[16][68];
    int tid = threadIdx.x, tx = tid & 15, ty = tid >> 4;
    size_t row0 = (size_t)blockIdx.y * 64;
    int col0 = blockIdx.x * 64;
    int a_row = tid >> 2,  a_ks = (tid & 3) << 2;
    int w_row = tid >> 4,  w_cs = (tid & 15) << 2;
    float2 p = ((const float2*)pts)[row0 + a_row];
    float acc[4][4] = {};
    for (int k0 = 0; k0 < 128; k0 += 16){
#pragma unroll
        for (int i = 0; i < 4; i++){
            int k = k0 + a_ks + i;
            As[a_ks+i][a_row] = fmaxf(p.x*fcw[k] + p.y*fcw[128 + k] + fcb[k], 0.0f);
        }
        *(float4*)&Ws[w_row][w_cs] = *(const float4*)(W + (size_t)(k0 + w_row)*Gg + col0 + w_cs);
        __syncthreads();
#pragma unroll
        for (int kk = 0; kk < 16; kk++){
            float a[4], bb[4];
#pragma unroll
            for (int i = 0; i < 4; i++) a[i]  = As[kk][ty*4 + i];
#pragma unroll
            for (int j = 0; j < 4; j++) bb[j] = Ws[kk][tx*4 + j];
#pragma unroll
            for (int i = 0; i < 4; i++)
#pragma unroll
                for (int j = 0; j < 4; j++) acc[i][j] += a[i]*bb[j];
        }
        __syncthreads();
    }
#pragma unroll
    for (int i = 0; i < 4; i++){
        size_t ro = (row0 + ty*4 + i)*(size_t)Gg + col0;
#pragma unroll
        for (int j = 0; j < 4; j++)
            g_GI[ro + tx*4 + j] = acc[i][j] + bias[col0 + tx*4 + j];
    }
}

// ---------------- w1e = enc_outs @ w1 ----------------
__global__ __launch_bounds__(256) void gemm_w1e(const float* __restrict__ W){
    __shared__ __align__(16) float As[16][68];
    __shared__ __align__(16) float Ws[16][68];
    int tid = threadIdx.x, tx = tid & 15, ty = tid >> 4;
    size_t row0 = (size_t)blockIdx.y * 64;
    int col0 = blockIdx.x * 64;
    int a_row = tid >> 2,  a_ks = (tid & 3) << 2;
    int w_row = tid >> 4,  w_cs = (tid & 15) << 2;
    float acc[4][4] = {};
    for (int k0 = 0; k0 < 128; k0 += 16){
        float4 av = *(const float4*)(g_enc + (row0 + a_row)*128 + k0 + a_ks);
        As[a_ks+0][a_row] = av.x; As[a_ks+1][a_row] = av.y;
        As[a_ks+2][a_row] = av.z; As[a_ks+3][a_row] = av.w;
        *(float4*)&Ws[w_row][w_cs] = *(const float4*)(W + (size_t)(k0 + w_row)*Hh + col0 + w_cs);
        __syncthreads();
#pragma unroll
        for (int kk = 0; kk < 16; kk++){
            float a[4], bb[4];
#pragma unroll
            for (int i = 0; i < 4; i++) a[i]  = As[kk][ty*4 + i];
#pragma unroll
            for (int j = 0; j < 4; j++) bb[j] = Ws[kk][tx*4 + j];
#pragma unroll
            for (int i = 0; i < 4; i++)
#pragma unroll
                for (int j = 0; j < 4; j++) acc[i][j] += a[i]*bb[j];
        }
        __syncthreads();
    }
#pragma unroll
    for (int i = 0; i < 4; i++){
        size_t ro = (row0 + ty*4 + i)*(size_t)Hh + col0;
#pragma unroll
        for (int j = 0; j < 4; j++) g_w1e[ro + tx*4 + j] = acc[i][j];
    }
}

// ---------------- encoder GRU step: gh GEMM + gate combine ----------------
__global__ __launch_bounds__(384) void enc_step(const float* __restrict__ whh,
                                                const float* __restrict__ bhh, int t){
    __shared__ float s_h[8][128];
    __shared__ float s_g[8][384];
    int r0 = blockIdx.x * 8, tid = threadIdx.x;
    for (int e = tid; e < 1024; e += 384){
        int r = e >> 7, m = e & 127;
        s_h[r][m] = g_h[(r0 + r)*Hh + m];
    }
    __syncthreads();
    float acc[8]; float bj = bhh[tid];
#pragma unroll
    for (int r = 0; r < 8; r++) acc[r] = bj;
#pragma unroll 4
    for (int k = 0; k < 128; k++){
        float wv = whh[k*Gg + tid];
#pragma unroll
        for (int r = 0; r < 8; r++) acc[r] += s_h[r][k]*wv;
    }
#pragma unroll
    for (int r = 0; r < 8; r++) s_g[r][tid] = acc[r];
    __syncthreads();
    for (int e = tid; e < 1024; e += 384){
        int r = e >> 7, m = e & 127;
        const float* gi = g_GI + ((size_t)(r0 + r)*Nn + t)*Gg;
        float rr = fsig(gi[m]       + s_g[r][m]);
        float zz = fsig(gi[m + 128] + s_g[r][m + 128]);
        float nn = ftanh(gi[m + 256] + rr*s_g[r][m + 256]);
        float hv = (1.0f - zz)*nn + zz*s_h[r][m];
        g_h[(r0 + r)*Hh + m] = hv;
        g_enc[((size_t)(r0 + r)*Nn + t)*Hh + m] = hv;
    }
}

// ---------------- decoder GRU step + q = hn @ w2 ----------------
__global__ __launch_bounds__(384) void dec_step(const float* __restrict__ wih,
                                                const float* __restrict__ whh,
                                                const float* __restrict__ bih,
                                                const float* __restrict__ bhh,
                                                const float* __restrict__ w2){
    __shared__ float s_in[8][128], s_h[8][128], s_hn[8][128];
    __shared__ float s_gi[8][384], s_gh[8][384];
    int r0 = blockIdx.x * 8, tid = threadIdx.x;
    for (int e = tid; e < 1024; e += 384){
        int r = e >> 7, m = e & 127;
        s_in[r][m] = g_decin[(r0 + r)*Hh + m];
        s_h[r][m]  = g_h[(r0 + r)*Hh + m];
    }
    __syncthreads();
    float aI[8], aH[8];
    float bi = bih[tid], bh = bhh[tid];
#pragma unroll
    for (int r = 0; r < 8; r++){ aI[r] = bi; aH[r] = bh; }
#pragma unroll 2
    for (int k = 0; k < 128; k++){
        float wi = wih[k*Gg + tid];
        float wh = whh[k*Gg + tid];
#pragma unroll
        for (int r = 0; r < 8; r++){ aI[r] += s_in[r][k]*wi; aH[r] += s_h[r][k]*wh; }
    }
#pragma unroll
    for (int r = 0; r < 8; r++){ s_gi[r][tid] = aI[r]; s_gh[r][tid] = aH[r]; }
    __syncthreads();
    for (int e = tid; e < 1024; e += 384){
        int r = e >> 7, m = e & 127;
        float rr = fsig(s_gi[r][m]       + s_gh[r][m]);
        float zz = fsig(s_gi[r][m + 128] + s_gh[r][m + 128]);
        float nn = ftanh(s_gi[r][m + 256] + rr*s_gh[r][m + 256]);
        float hv = (1.0f - zz)*nn + zz*s_h[r][m];
        g_h[(r0 + r)*Hh + m] = hv;
        s_hn[r][m] = hv;
    }
    __syncthreads();
    for (int e = tid; e < 1024; e += 384){
        int r = e >> 7, m = e & 127;
        float a = 0.0f;
#pragma unroll 4
        for (int k = 0; k < 128; k++) a += s_hn[r][k]*w2[k*Hh + m];
        g_q[(r0 + r)*Hh + m] = a;
    }
}

// ------- scores + exact-JAX gumbel sample + log_softmax + state update -------
__global__ __launch_bounds__(256) void score_step(const float* __restrict__ vt,
                                                  float* seq_out, float* lp_out, int t){
    int b = blockIdx.x, tid = threadIdx.x;
    __shared__ __align__(16) float sq[128];
    __shared__ float ssc[256];
    __shared__ float rv[256]; __shared__ int ri[256];
    __shared__ float rm[256]; __shared__ float rs[256];
    __shared__ int ssel;
    if (tid < 128) sq[tid] = g_q[b*Hh + tid];
    __syncthreads();
    int lane = tid & 31, wp = tid >> 5;
    float4 v4 = ((const float4*)vt)[lane];
    float4 q4 = ((const float4*)sq)[lane];
    const unsigned char* mrow = g_mask + b*Nn;
    const float4* wb = (const float4*)(g_w1e + (size_t)b*Nn*Hh);
#pragma unroll 1
    for (int i = 0; i < 32; i++){
        int n = wp*32 + i;
        float sc = -INFINITY;
        if (!mrow[n]){                     // warp-uniform branch
            float4 e = wb[(size_t)n*32 + lane];
            float pp = ftanh(e.x + q4.x)*v4.x + ftanh(e.y + q4.y)*v4.y
                     + ftanh(e.z + q4.z)*v4.z + ftanh(e.w + q4.w)*v4.w;
#pragma unroll
            for (int o = 16; o; o >>= 1) pp += __shfl_xor_sync(0xffffffffu, pp, o);
            sc = pp;
        }
        if (lane == 0) ssc[n] = sc;
    }
    __syncthreads();

    float logit = ssc[tid];
    // k = fold_in(key(42), t) = threefry((0,42), (0,t))
    unsigned fk0, fk1; tfry(0u, 42u, 0u, (unsigned)t, fk0, fk1);
    // PARTITIONABLE threefry random_bits, bit_width=32:
    //   (c_hi, c_lo) = iota_2x32_shape -> (0, i) for i < 2^32
    //   bits1, bits2 = threefry2x32(key, c_hi, c_lo)
    //   bits = bits1 XOR bits2        <-- the <64-bit path XORs the two words
    unsigned i32 = (unsigned)(b*Nn + tid);
    unsigned o0, o1;
    tfry(fk0, fk1, 0u, i32, o0, o1);
    unsigned wbits = o0 ^ o1;
    float fl = __uint_as_float((wbits >> 9) | 0x3f800000u) - 1.0f;   // [0,1)
    const float TINY = 1.17549435e-38f;
    float u = fmaxf(TINY, fl + TINY);   // fl*(1-tiny)+tiny == fl+tiny in fp32
    float gmb = -logf(-logf(u));
    float pert = logit + gmb;                 // -inf stays -inf

    rv[tid] = pert; ri[tid] = tid; rm[tid] = logit;
    __syncthreads();
    for (int s = 128; s; s >>= 1){
        if (tid < s){
            float v2 = rv[tid+s]; int i2 = ri[tid+s];
            if (v2 > rv[tid] || (v2 == rv[tid] && i2 < ri[tid])){ rv[tid] = v2; ri[tid] = i2; }
            rm[tid] = fmaxf(rm[tid], rm[tid+s]);
        }
        __syncthreads();
    }
    float M = rm[0];
    rs[tid] = expf(logit - M);                // exp(-inf)=0 for masked
    __syncthreads();
    for (int s = 128; s; s >>= 1){
        if (tid < s) rs[tid] += rs[tid+s];
        __syncthreads();
    }
    if (tid == 0){
        int sel = ri[0]; ssel = sel;
        float lp = ssc[sel] - M - logf(rs[0]);
        g_mask[b*Nn + sel] = 1;
        if (seq_out) seq_out[b*Nn + t] = (float)sel;
        float acc = g_logp[b] + lp;
        g_logp[b] = acc;
        if (t == Nn - 1 && lp_out) lp_out[b] = acc;
    }
    __syncthreads();
    int sel = ssel;
    if (tid < Hh) g_decin[b*Hh + tid] = g_enc[((size_t)b*Nn + sel)*Hh + tid];
}

// ---------------- launch ----------------
extern "C" void kernel_launch(void* const* d_in, const int* in_sizes, int n_in,
                              void* d_out, int out_size){
    const float* points  = (const float*)d_in[0];
    const float* fc_w    = (const float*)d_in[1];
    const float* fc_b    = (const float*)d_in[2];
    const float* enc_wih = (const float*)d_in[3];
    const float* enc_whh = (const float*)d_in[4];
    const float* enc_bih = (const float*)d_in[5];
    const float* enc_bhh = (const float*)d_in[6];
    const float* dec_wih = (const float*)d_in[7];
    const float* dec_whh = (const float*)d_in[8];
    const float* dec_bih = (const float*)d_in[9];
    const float* dec_bhh = (const float*)d_in[10];
    const float* w1      = (const float*)d_in[11];
    const float* w2      = (const float*)d_in[12];
    const float* vt      = (const float*)d_in[13];
    const float* sp_w    = (const float*)d_in[14];
    const float* sp_b    = (const float*)d_in[15];

    float* out = (float*)d_out;
    float* seq_out = nullptr; float* lp_out = nullptr;
    if (out_size >= Bsz*Nn + Bsz){ seq_out = out; lp_out = out + Bsz*Nn; }
    else if (out_size >= Bsz*Nn){ seq_out = out; }
    else { lp_out = out; }

    init_k<<<Bsz, 256>>>(points, sp_w, sp_b);
    gemm_gi<<<dim3(Gg/64, (Bsz*Nn)/64), 256>>>(points, fc_w, fc_b, enc_wih, enc_bih);
    for (int t = 0; t < Nn; t++)
        enc_step<<<64, 384>>>(enc_whh, enc_bhh, t);
    gemm_w1e<<<dim3(Hh/64, (Bsz*Nn)/64), 256>>>(w1);
    for (int t = 0; t < Nn; t++){
        dec_step<<<64, 384>>>(dec_wih, dec_whh, dec_bih, dec_bhh, w2);
        score_step<<<Bsz, 256>>>(vt, seq_out, lp_out, t);
    }
}

// round 17
// speedup vs baseline: 1.2786x; 1.2786x over previous
#include <cuda_runtime.h>
#include <math.h>
#include <stdint.h>

#define Bsz 512
#define Nn  256
#define Hh  128
#define Gg  384   // 3*H

// ---------------- device scratch (no runtime allocs allowed) ----------------
__device__ float g_GI[(size_t)Bsz*Nn*Gg];    // encoder input gates (x@wih+bih)
__device__ float g_enc[(size_t)Bsz*Nn*Hh];   // encoder outputs
__device__ float g_w1e[(size_t)Bsz*Nn*Hh];   // enc_outs @ w1
__device__ float g_h[Bsz*Hh];                // GRU hidden (enc then dec)
__device__ float g_decin[Bsz*Hh];            // decoder input vector
__device__ float g_q[Bsz*Hh];                // hn @ w2
__device__ float g_logp[Bsz];
__device__ unsigned char g_mask[Bsz*Nn];

// ---------------- math helpers (robust to fast-math) ----------------
__device__ __forceinline__ float fsig(float x){
    return 1.0f/(1.0f + exp2f(-1.4426950408889634f*x));
}
__device__ __forceinline__ float ftanh(float x){
    float e = exp2f(2.8853900817779268f*x);     // e^(2x)
    return 1.0f - 2.0f/(e + 1.0f);
}

// ---------------- JAX threefry2x32 (exact, 20 rounds) ----------------
__device__ __forceinline__ unsigned rotl(unsigned v, int s){ return (v<<s)|(v>>(32-s)); }
__device__ __forceinline__ void tfry(unsigned k0, unsigned k1,
                                     unsigned x0, unsigned x1,
                                     unsigned &o0, unsigned &o1){
    unsigned k2 = k0 ^ k1 ^ 0x1BD11BDAu;
    x0 += k0; x1 += k1;
    x0+=x1; x1=rotl(x1,13); x1^=x0;  x0+=x1; x1=rotl(x1,15); x1^=x0;
    x0+=x1; x1=rotl(x1,26); x1^=x0;  x0+=x1; x1=rotl(x1, 6); x1^=x0;
    x0 += k1; x1 += k2 + 1u;
    x0+=x1; x1=rotl(x1,17); x1^=x0;  x0+=x1; x1=rotl(x1,29); x1^=x0;
    x0+=x1; x1=rotl(x1,16); x1^=x0;  x0+=x1; x1=rotl(x1,24); x1^=x0;
    x0 += k2; x1 += k0 + 2u;
    x0+=x1; x1=rotl(x1,13); x1^=x0;  x0+=x1; x1=rotl(x1,15); x1^=x0;
    x0+=x1; x1=rotl(x1,26); x1^=x0;  x0+=x1; x1=rotl(x1, 6); x1^=x0;
    x0 += k0; x1 += k1 + 3u;
    x0+=x1; x1=rotl(x1,17); x1^=x0;  x0+=x1; x1=rotl(x1,29); x1^=x0;
    x0+=x1; x1=rotl(x1,16); x1^=x0;  x0+=x1; x1=rotl(x1,24); x1^=x0;
    x0 += k1; x1 += k2 + 4u;
    x0+=x1; x1=rotl(x1,13); x1^=x0;  x0+=x1; x1=rotl(x1,15); x1^=x0;
    x0+=x1; x1=rotl(x1,26); x1^=x0;  x0+=x1; x1=rotl(x1, 6); x1^=x0;
    x0 += k2; x1 += k0 + 5u;
    o0 = x0; o1 = x1;
}

// ---------------- init: mask=0, h=0, logp=0, dec_input0 ----------------
__global__ __launch_bounds__(256) void init_k(const float* __restrict__ pts,
                                              const float* __restrict__ spw,
                                              const float* __restrict__ spb){
    int b = blockIdx.x, tid = threadIdx.x;
    __shared__ float s0[256], s1[256];
    float2 p = ((const float2*)pts)[b*Nn + tid];
    s0[tid] = p.x; s1[tid] = p.y;
    __syncthreads();
    for (int s = 128; s; s >>= 1){
        if (tid < s){ s0[tid] += s0[tid+s]; s1[tid] += s1[tid+s]; }
        __syncthreads();
    }
    float m0 = s0[0] * (1.0f/256.0f);
    float m1 = s1[0] * (1.0f/256.0f);
    g_mask[b*Nn + tid] = 0;
    if (tid < Hh){
        g_h[b*Hh + tid] = 0.0f;
        g_decin[b*Hh + tid] = m0*spw[tid] + m1*spw[Hh + tid] + spb[tid];
    }
    if (tid == 0) g_logp[b] = 0.0f;
}

// -------- GI = relu(points@fc_w+fc_b) @ enc_wih + enc_bih (fused A) --------
__global__ __launch_bounds__(256) void gemm_gi(const float* __restrict__ pts,
                                               const float* __restrict__ fcw,
                                               const float* __restrict__ fcb,
                                               const float* __restrict__ W,
                                               const float* __restrict__ bias){
    __shared__ __align__(16) float As[16][68];
    __shared__ __align__(16) float Ws[16][68];
    int tid = threadIdx.x, tx = tid & 15, ty = tid >> 4;
    size_t row0 = (size_t)blockIdx.y * 64;
    int col0 = blockIdx.x * 64;
    int a_row = tid >> 2,  a_ks = (tid & 3) << 2;
    int w_row = tid >> 4,  w_cs = (tid & 15) << 2;
    float2 p = ((const float2*)pts)[row0 + a_row];
    float acc[4][4] = {};
    for (int k0 = 0; k0 < 128; k0 += 16){
#pragma unroll
        for (int i = 0; i < 4; i++){
            int k = k0 + a_ks + i;
            As[a_ks+i][a_row] = fmaxf(p.x*fcw[k] + p.y*fcw[128 + k] + fcb[k], 0.0f);
        }
        *(float4*)&Ws[w_row][w_cs] = *(const float4*)(W + (size_t)(k0 + w_row)*Gg + col0 + w_cs);
        __syncthreads();
#pragma unroll
        for (int kk = 0; kk < 16; kk++){
            float a[4], bb[4];
#pragma unroll
            for (int i = 0; i < 4; i++) a[i]  = As[kk][ty*4 + i];
#pragma unroll
            for (int j = 0; j < 4; j++) bb[j] = Ws[kk][tx*4 + j];
#pragma unroll
            for (int i = 0; i < 4; i++)
#pragma unroll
                for (int j = 0; j < 4; j++) acc[i][j] += a[i]*bb[j];
        }
        __syncthreads();
    }
#pragma unroll
    for (int i = 0; i < 4; i++){
        size_t ro = (row0 + ty*4 + i)*(size_t)Gg + col0;
#pragma unroll
        for (int j = 0; j < 4; j++)
            g_GI[ro + tx*4 + j] = acc[i][j] + bias[col0 + tx*4 + j];
    }
}

// ---------------- w1e = enc_outs @ w1 ----------------
__global__ __launch_bounds__(256) void gemm_w1e(const float* __restrict__ W){
    __shared__ __align__(16) float As[16][68];
    __shared__ __align__(16) float Ws[16][68];
    int tid = threadIdx.x, tx = tid & 15, ty = tid >> 4;
    size_t row0 = (size_t)blockIdx.y * 64;
    int col0 = blockIdx.x * 64;
    int a_row = tid >> 2,  a_ks = (tid & 3) << 2;
    int w_row = tid >> 4,  w_cs = (tid & 15) << 2;
    float acc[4][4] = {};
    for (int k0 = 0; k0 < 128; k0 += 16){
        float4 av = *(const float4*)(g_enc + (row0 + a_row)*128 + k0 + a_ks);
        As[a_ks+0][a_row] = av.x; As[a_ks+1][a_row] = av.y;
        As[a_ks+2][a_row] = av.z; As[a_ks+3][a_row] = av.w;
        *(float4*)&Ws[w_row][w_cs] = *(const float4*)(W + (size_t)(k0 + w_row)*Hh + col0 + w_cs);
        __syncthreads();
#pragma unroll
        for (int kk = 0; kk < 16; kk++){
            float a[4], bb[4];
#pragma unroll
            for (int i = 0; i < 4; i++) a[i]  = As[kk][ty*4 + i];
#pragma unroll
            for (int j = 0; j < 4; j++) bb[j] = Ws[kk][tx*4 + j];
#pragma unroll
            for (int i = 0; i < 4; i++)
#pragma unroll
                for (int j = 0; j < 4; j++) acc[i][j] += a[i]*bb[j];
        }
        __syncthreads();
    }
#pragma unroll
    for (int i = 0; i < 4; i++){
        size_t ro = (row0 + ty*4 + i)*(size_t)Hh + col0;
#pragma unroll
        for (int j = 0; j < 4; j++) g_w1e[ro + tx*4 + j] = acc[i][j];
    }
}

// -------- encoder GRU step: 4 rows/block, grid 128, float4 h in smem --------
__global__ __launch_bounds__(384) void enc_step(const float* __restrict__ whh,
                                                const float* __restrict__ bhh, int t){
    __shared__ __align__(16) float4 s_h4[128];   // [k] -> rows 0..3
    __shared__ float s_g[4][384];
    int r0 = blockIdx.x*4, tid = threadIdx.x;
    if (tid < 128){
        float4 v;
        v.x = g_h[(r0+0)*Hh + tid];
        v.y = g_h[(r0+1)*Hh + tid];
        v.z = g_h[(r0+2)*Hh + tid];
        v.w = g_h[(r0+3)*Hh + tid];
        s_h4[tid] = v;
    }
    __syncthreads();
    float bj = bhh[tid];
    float a0 = bj, a1 = bj, a2 = bj, a3 = bj;
#pragma unroll 4
    for (int k = 0; k < 128; k++){
        float wv = whh[k*Gg + tid];
        float4 h4 = s_h4[k];
        a0 += h4.x*wv; a1 += h4.y*wv; a2 += h4.z*wv; a3 += h4.w*wv;
    }
    s_g[0][tid] = a0; s_g[1][tid] = a1; s_g[2][tid] = a2; s_g[3][tid] = a3;
    __syncthreads();
    for (int e = tid; e < 512; e += 384){
        int r = e >> 7, m = e & 127;
        const float* gi = g_GI + ((size_t)(r0 + r)*Nn + t)*Gg;
        float hprev = ((const float*)s_h4)[m*4 + r];
        float rr = fsig(gi[m]       + s_g[r][m]);
        float zz = fsig(gi[m + 128] + s_g[r][m + 128]);
        float nn = ftanh(gi[m + 256] + rr*s_g[r][m + 256]);
        float hv = (1.0f - zz)*nn + zz*hprev;
        g_h[(r0 + r)*Hh + m] = hv;
        g_enc[((size_t)(r0 + r)*Nn + t)*Hh + m] = hv;
    }
}

// ---- decoder GRU step + q = hn @ w2 : 4 rows/block, grid 128, float4 smem ----
__global__ __launch_bounds__(384) void dec_step(const float* __restrict__ wih,
                                                const float* __restrict__ whh,
                                                const float* __restrict__ bih,
                                                const float* __restrict__ bhh,
                                                const float* __restrict__ w2){
    __shared__ __align__(16) float4 s_in4[128], s_h4[128];
    __shared__ float s_gi[4][384], s_gh[4][384];
    __shared__ float s_hn[4][128];
    int r0 = blockIdx.x*4, tid = threadIdx.x;
    if (tid < 128){
        float4 vi, vh;
        vi.x = g_decin[(r0+0)*Hh + tid]; vh.x = g_h[(r0+0)*Hh + tid];
        vi.y = g_decin[(r0+1)*Hh + tid]; vh.y = g_h[(r0+1)*Hh + tid];
        vi.z = g_decin[(r0+2)*Hh + tid]; vh.z = g_h[(r0+2)*Hh + tid];
        vi.w = g_decin[(r0+3)*Hh + tid]; vh.w = g_h[(r0+3)*Hh + tid];
        s_in4[tid] = vi; s_h4[tid] = vh;
    }
    __syncthreads();
    float bi = bih[tid], bh = bhh[tid];
    float i0 = bi, i1 = bi, i2 = bi, i3 = bi;
    float h0 = bh, h1 = bh, h2 = bh, h3 = bh;
#pragma unroll 4
    for (int k = 0; k < 128; k++){
        float wi = wih[k*Gg + tid];
        float wh = whh[k*Gg + tid];
        float4 v4 = s_in4[k];
        float4 h4 = s_h4[k];
        i0 += v4.x*wi; i1 += v4.y*wi; i2 += v4.z*wi; i3 += v4.w*wi;
        h0 += h4.x*wh; h1 += h4.y*wh; h2 += h4.z*wh; h3 += h4.w*wh;
    }
    s_gi[0][tid] = i0; s_gi[1][tid] = i1; s_gi[2][tid] = i2; s_gi[3][tid] = i3;
    s_gh[0][tid] = h0; s_gh[1][tid] = h1; s_gh[2][tid] = h2; s_gh[3][tid] = h3;
    __syncthreads();
    for (int e = tid; e < 512; e += 384){
        int r = e >> 7, m = e & 127;
        float hprev = ((const float*)s_h4)[m*4 + r];
        float rr = fsig(s_gi[r][m]       + s_gh[r][m]);
        float zz = fsig(s_gi[r][m + 128] + s_gh[r][m + 128]);
        float nn = ftanh(s_gi[r][m + 256] + rr*s_gh[r][m + 256]);
        float hv = (1.0f - zz)*nn + zz*hprev;
        g_h[(r0 + r)*Hh + m] = hv;
        s_hn[r][m] = hv;
    }
    __syncthreads();
    for (int e = tid; e < 512; e += 384){
        int r = e >> 7, m = e & 127;
        float a = 0.0f;
#pragma unroll 4
        for (int k = 0; k < 128; k++) a += s_hn[r][k]*w2[k*Hh + m];
        g_q[(r0 + r)*Hh + m] = a;
    }
}

// ------- scores + exact-JAX gumbel sample + log_softmax + state update -------
__global__ __launch_bounds__(256) void score_step(const float* __restrict__ vt,
                                                  float* seq_out, float* lp_out, int t){
    int b = blockIdx.x, tid = threadIdx.x;
    __shared__ __align__(16) float sq[128];
    __shared__ float ssc[256];
    __shared__ float rv[256]; __shared__ int ri[256];
    __shared__ float rm[256]; __shared__ float rs[256];
    __shared__ int ssel;
    if (tid < 128) sq[tid] = g_q[b*Hh + tid];
    __syncthreads();
    int lane = tid & 31, wp = tid >> 5;
    float4 v4 = ((const float4*)vt)[lane];
    float4 q4 = ((const float4*)sq)[lane];
    const unsigned char* mrow = g_mask + b*Nn;
    const float4* wb = (const float4*)(g_w1e + (size_t)b*Nn*Hh);
#pragma unroll 1
    for (int i = 0; i < 32; i++){
        int n = wp*32 + i;
        float sc = -INFINITY;
        if (!mrow[n]){                     // warp-uniform branch
            float4 e = wb[(size_t)n*32 + lane];
            float pp = ftanh(e.x + q4.x)*v4.x + ftanh(e.y + q4.y)*v4.y
                     + ftanh(e.z + q4.z)*v4.z + ftanh(e.w + q4.w)*v4.w;
#pragma unroll
            for (int o = 16; o; o >>= 1) pp += __shfl_xor_sync(0xffffffffu, pp, o);
            sc = pp;
        }
        if (lane == 0) ssc[n] = sc;
    }
    __syncthreads();

    float logit = ssc[tid];
    // k = fold_in(key(42), t) = threefry((0,42), (0,t))
    unsigned fk0, fk1; tfry(0u, 42u, 0u, (unsigned)t, fk0, fk1);
    // PARTITIONABLE threefry random_bits (bit_width=32): bits = o0 ^ o1,
    // counter = (0, flat_index)
    unsigned i32 = (unsigned)(b*Nn + tid);
    unsigned o0, o1;
    tfry(fk0, fk1, 0u, i32, o0, o1);
    unsigned wbits = o0 ^ o1;
    float fl = __uint_as_float((wbits >> 9) | 0x3f800000u) - 1.0f;   // [0,1)
    const float TINY = 1.17549435e-38f;
    float u = fmaxf(TINY, fl + TINY);
    float gmb = -logf(-logf(u));
    float pert = logit + gmb;                 // -inf stays -inf

    rv[tid] = pert; ri[tid] = tid; rm[tid] = logit;
    __syncthreads();
    for (int s = 128; s; s >>= 1){
        if (tid < s){
            float v2 = rv[tid+s]; int i2 = ri[tid+s];
            if (v2 > rv[tid] || (v2 == rv[tid] && i2 < ri[tid])){ rv[tid] = v2; ri[tid] = i2; }
            rm[tid] = fmaxf(rm[tid], rm[tid+s]);
        }
        __syncthreads();
    }
    float M = rm[0];
    rs[tid] = expf(logit - M);                // exp(-inf)=0 for masked
    __syncthreads();
    for (int s = 128; s; s >>= 1){
        if (tid < s) rs[tid] += rs[tid+s];
        __syncthreads();
    }
    if (tid == 0){
        int sel = ri[0]; ssel = sel;
        float lp = ssc[sel] - M - logf(rs[0]);
        g_mask[b*Nn + sel] = 1;
        if (seq_out) seq_out[b*Nn + t] = (float)sel;
        float acc = g_logp[b] + lp;
        g_logp[b] = acc;
        if (t == Nn - 1 && lp_out) lp_out[b] = acc;
    }
    __syncthreads();
    int sel = ssel;
    if (tid < Hh) g_decin[b*Hh + tid] = g_enc[((size_t)b*Nn + sel)*Hh + tid];
}

// ---------------- launch ----------------
extern "C" void kernel_launch(void* const* d_in, const int* in_sizes, int n_in,
                              void* d_out, int out_size){
    const float* points  = (const float*)d_in[0];
    const float* fc_w    = (const float*)d_in[1];
    const float* fc_b    = (const float*)d_in[2];
    const float* enc_wih = (const float*)d_in[3];
    const float* enc_whh = (const float*)d_in[4];
    const float* enc_bih = (const float*)d_in[5];
    const float* enc_bhh = (const float*)d_in[6];
    const float* dec_wih = (const float*)d_in[7];
    const float* dec_whh = (const float*)d_in[8];
    const float* dec_bih = (const float*)d_in[9];
    const float* dec_bhh = (const float*)d_in[10];
    const float* w1      = (const float*)d_in[11];
    const float* w2      = (const float*)d_in[12];
    const float* vt      = (const float*)d_in[13];
    const float* sp_w    = (const float*)d_in[14];
    const float* sp_b    = (const float*)d_in[15];

    float* out = (float*)d_out;
    float* seq_out = nullptr; float* lp_out = nullptr;
    if (out_size >= Bsz*Nn + Bsz){ seq_out = out; lp_out = out + Bsz*Nn; }
    else if (out_size >= Bsz*Nn){ seq_out = out; }
    else { lp_out = out; }

    init_k<<<Bsz, 256>>>(points, sp_w, sp_b);
    gemm_gi<<<dim3(Gg/64, (Bsz*Nn)/64), 256>>>(points, fc_w, fc_b, enc_wih, enc_bih);
    for (int t = 0; t < Nn; t++)
        enc_step<<<128, 384>>>(enc_whh, enc_bhh, t);
    gemm_w1e<<<dim3(Hh/64, (Bsz*Nn)/64), 256>>>(w1);
    for (int t = 0; t < Nn; t++){
        dec_step<<<128, 384>>>(dec_wih, dec_whh, dec_bih, dec_bhh, w2);
        score_step<<<Bsz, 256>>>(vt, seq_out, lp_out, t);
    }
}